// round 3
// baseline (speedup 1.0000x reference)
#include <cuda_runtime.h>
#include <cstdint>

#define N_NODES 50000
#define N_EDGES 1600000
#define NUM_FEATURES 500
#define HIDDEN 64
#define NUM_CLASSES 40
#define NUM_LAYERS 4
#define STEP_F 0.1f

#define SCAN_BLK 1024
#define SCAN_NBLK ((N_NODES + SCAN_BLK - 1) / SCAN_BLK)   // 49

// ---------------- device scratch (static, allocation-free) ----------------
__device__ float g_ha[N_NODES * HIDDEN];
__device__ float g_hb[N_NODES * HIDDEN];
__device__ float g_x0[N_NODES * HIDDEN];
__device__ unsigned long long g_srccoef[N_EDGES];   // packed {src, coef}
__device__ int   g_rowptr[N_NODES + 1];
__device__ int   g_degcnt[N_NODES];
__device__ int   g_fill[N_NODES];
__device__ float g_deginv[N_NODES];
__device__ float g_W[HIDDEN * HIDDEN];              // symmetric W_eff
__device__ int   g_blocksums[SCAN_NBLK];
__device__ int   g_blockoff[SCAN_NBLK];

// ---------------- graph preprocessing ----------------
__global__ void zero_counts() {
    int i = blockIdx.x * blockDim.x + threadIdx.x;
    if (i < N_NODES) { g_degcnt[i] = 0; g_fill[i] = 0; }
}

__global__ void count_deg(const int* __restrict__ col) {
    int e = blockIdx.x * blockDim.x + threadIdx.x;
    if (e < N_EDGES) atomicAdd(&g_degcnt[col[e]], 1);
}

__global__ void deg_inv_kernel() {
    int i = blockIdx.x * blockDim.x + threadIdx.x;
    if (i < N_NODES) {
        int c = g_degcnt[i];
        g_deginv[i] = (c > 0) ? rsqrtf((float)c) : 0.0f;
    }
}

// ---- multi-block exclusive scan of g_degcnt -> g_rowptr ----
__global__ void scan1() {
    __shared__ int s[SCAN_BLK];
    int b = blockIdx.x, t = threadIdx.x;
    int i = b * SCAN_BLK + t;
    int v = (i < N_NODES) ? g_degcnt[i] : 0;
    s[t] = v;
    __syncthreads();
#pragma unroll
    for (int off = 1; off < SCAN_BLK; off <<= 1) {
        int tv = 0;
        if (t >= off) tv = s[t - off];
        __syncthreads();
        if (t >= off) s[t] += tv;
        __syncthreads();
    }
    if (i < N_NODES) g_rowptr[i] = s[t] - v;     // block-local exclusive
    if (t == SCAN_BLK - 1) g_blocksums[b] = s[t];
}

__global__ void scan2() {
    if (threadIdx.x == 0) {
        int run = 0;
        for (int b = 0; b < SCAN_NBLK; b++) {
            g_blockoff[b] = run;
            run += g_blocksums[b];
        }
        g_rowptr[N_NODES] = run;
    }
}

__global__ void scan3() {
    int i = blockIdx.x * blockDim.x + threadIdx.x;
    if (i < N_NODES) g_rowptr[i] += g_blockoff[i >> 10];
}

__global__ void fill_csr(const int* __restrict__ row, const int* __restrict__ col) {
    int e = blockIdx.x * blockDim.x + threadIdx.x;
    if (e >= N_EDGES) return;
    int v = col[e];
    int r = row[e];
    int slot = g_rowptr[v] + atomicAdd(&g_fill[v], 1);
    float cf = g_deginv[r] * g_deginv[v];
    g_srccoef[slot] = (unsigned long long)(unsigned)r
                    | ((unsigned long long)__float_as_uint(cf) << 32);
}

// ---------------- pairwise weight (symmetric): W_eff = sym(triu(pw,1)) + diag(q*rowsum|W|+r)
__global__ void weff_kernel(const float* __restrict__ pw) {
    int i = threadIdx.x;
    if (i >= HIDDEN) return;
    float q  = pw[i * (HIDDEN + 2) + HIDDEN];
    float rr = pw[i * (HIDDEN + 2) + HIDDEN + 1];
    float s = 0.0f;
    for (int j = 0; j < HIDDEN; j++) {
        float w = 0.0f;
        if (i < j)      w = pw[i * (HIDDEN + 2) + j];
        else if (i > j) w = pw[j * (HIDDEN + 2) + i];
        s += fabsf(w);
        g_W[i * HIDDEN + j] = w;
    }
    g_W[i * HIDDEN + i] = q * s + rr;
}

// ---------------- encoder SGEMM: h = x @ enc_w^T ; also x0 = h ----------------
#define BM 128
#define BK 16
#define TM 8
#define TN 4

__global__ void encoder_gemm(const float* __restrict__ A, const float* __restrict__ B) {
    __shared__ float As[BK][BM + 4];
    __shared__ float Bs[BK][HIDDEN + 4];

    int tid = threadIdx.x;        // 256 threads
    int tx = tid & 15;            // 16 col groups of TN=4
    int ty = tid >> 4;            // 16 row groups of TM=8
    int bm0 = blockIdx.x * BM;
    const int M = N_NODES, N = HIDDEN, K = NUM_FEATURES;

    float acc[TM][TN];
#pragma unroll
    for (int r = 0; r < TM; r++)
#pragma unroll
        for (int c = 0; c < TN; c++) acc[r][c] = 0.0f;

    for (int kb = 0; kb < K; kb += BK) {
#pragma unroll
        for (int it = 0; it < 2; it++) {
            int j = tid + it * 256;
            int arow = j >> 2;
            int kc4 = (j & 3) * 4;
            int grow = bm0 + arow;
#pragma unroll
            for (int i = 0; i < 4; i++) {
                int gc = kb + kc4 + i;
                float v = (grow < M && gc < K) ? A[(size_t)grow * K + gc] : 0.0f;
                As[kc4 + i][arow] = v;
            }
        }
        {
            int j = tid;
            int nrow = j >> 2;
            int kc4 = (j & 3) * 4;
#pragma unroll
            for (int i = 0; i < 4; i++) {
                int gc = kb + kc4 + i;
                float v = (gc < K) ? B[(size_t)nrow * K + gc] : 0.0f;
                Bs[kc4 + i][nrow] = v;
            }
        }
        __syncthreads();
#pragma unroll
        for (int k = 0; k < BK; k++) {
            float4 a0 = *(const float4*)&As[k][ty * TM];
            float4 a1 = *(const float4*)&As[k][ty * TM + 4];
            float4 b  = *(const float4*)&Bs[k][tx * TN];
            float ar[TM] = {a0.x, a0.y, a0.z, a0.w, a1.x, a1.y, a1.z, a1.w};
            float bc[TN] = {b.x, b.y, b.z, b.w};
#pragma unroll
            for (int r = 0; r < TM; r++)
#pragma unroll
                for (int c = 0; c < TN; c++)
                    acc[r][c] += ar[r] * bc[c];
        }
        __syncthreads();
    }

    int col = tx * TN;
#pragma unroll
    for (int r = 0; r < TM; r++) {
        int row = bm0 + ty * TM + r;
        if (row >= M) continue;
        float4 o = make_float4(acc[r][0], acc[r][1], acc[r][2], acc[r][3]);
        *(float4*)&g_ha[(size_t)row * HIDDEN + col] = o;
        *(float4*)&g_x0[(size_t)row * HIDDEN + col] = o;
    }
}

// ---------------- fused layer: gather + agg@W + pointwise update (+ decoder on LAST)
// one warp per node; 8 warps per block. IN_A selects h ping-pong direction.
template <bool IN_A, bool LAST>
__global__ void layer_kernel(const float* __restrict__ ext,
                             const float* __restrict__ betap,
                             const float* __restrict__ dec,
                             float* __restrict__ out) {
    __shared__ float W_s[HIDDEN * HIDDEN];          // 16 KB
    __shared__ float agg_s[8][HIDDEN];              // 2 KB
    __shared__ float ext_s[HIDDEN];
    __shared__ float dec_s[LAST ? HIDDEN * NUM_CLASSES : 1];

    const float* __restrict__ h_in  = IN_A ? g_ha : g_hb;
    float*       __restrict__ h_out = IN_A ? g_hb : g_ha;

    int tid  = threadIdx.x;          // 256
    int warp = tid >> 5;
    int lane = tid & 31;

    // stage W (symmetric, so row-major == needed layout)
#pragma unroll
    for (int i = 0; i < HIDDEN * HIDDEN / 256; i++)
        W_s[tid + i * 256] = g_W[tid + i * 256];
    if (tid < HIDDEN) ext_s[tid] = ext[tid];
    if (LAST) {
        for (int idx = tid; idx < HIDDEN * NUM_CLASSES; idx += 256) {
            int c = idx / HIDDEN, k = idx % HIDDEN;
            dec_s[k * NUM_CLASSES + c] = dec[idx];   // transpose to [k][c]
        }
    }
    __syncthreads();

    int node = blockIdx.x * 8 + warp;
    if (node >= N_NODES) return;

    // ---- gather: acc = sum coef * h_in[src], lanes cover 64 floats as float2
    int beg = g_rowptr[node];
    int end = g_rowptr[node + 1];
    float2 acc = make_float2(0.0f, 0.0f);
    int e = beg;
    for (; e + 3 < end; e += 4) {
        unsigned long long p0 = __ldg(&g_srccoef[e]);
        unsigned long long p1 = __ldg(&g_srccoef[e + 1]);
        unsigned long long p2 = __ldg(&g_srccoef[e + 2]);
        unsigned long long p3 = __ldg(&g_srccoef[e + 3]);
        const float2* r0 = (const float2*)(h_in + (size_t)(unsigned)(p0 & 0xffffffffu) * HIDDEN) + lane;
        const float2* r1 = (const float2*)(h_in + (size_t)(unsigned)(p1 & 0xffffffffu) * HIDDEN) + lane;
        const float2* r2 = (const float2*)(h_in + (size_t)(unsigned)(p2 & 0xffffffffu) * HIDDEN) + lane;
        const float2* r3 = (const float2*)(h_in + (size_t)(unsigned)(p3 & 0xffffffffu) * HIDDEN) + lane;
        float2 v0 = __ldg(r0), v1 = __ldg(r1), v2 = __ldg(r2), v3 = __ldg(r3);
        float c0 = __uint_as_float((unsigned)(p0 >> 32));
        float c1 = __uint_as_float((unsigned)(p1 >> 32));
        float c2 = __uint_as_float((unsigned)(p2 >> 32));
        float c3 = __uint_as_float((unsigned)(p3 >> 32));
        acc.x += c0 * v0.x; acc.y += c0 * v0.y;
        acc.x += c1 * v1.x; acc.y += c1 * v1.y;
        acc.x += c2 * v2.x; acc.y += c2 * v2.y;
        acc.x += c3 * v3.x; acc.y += c3 * v3.y;
    }
    for (; e < end; e++) {
        unsigned long long p0 = __ldg(&g_srccoef[e]);
        const float2* r0 = (const float2*)(h_in + (size_t)(unsigned)(p0 & 0xffffffffu) * HIDDEN) + lane;
        float2 v0 = __ldg(r0);
        float c0 = __uint_as_float((unsigned)(p0 >> 32));
        acc.x += c0 * v0.x; acc.y += c0 * v0.y;
    }

    // ---- matvec: o[c] = sum_k agg[k] * W[k][c]  (W symmetric)
    agg_s[warp][lane * 2]     = acc.x;
    agg_s[warp][lane * 2 + 1] = acc.y;
    __syncwarp();

    float o0 = 0.0f, o1 = 0.0f;
    int c0i = lane * 2;
#pragma unroll
    for (int k = 0; k < HIDDEN; k++) {
        float a = agg_s[warp][k];                         // broadcast
        float2 w = *(const float2*)&W_s[k * HIDDEN + c0i];
        o0 += a * w.x;
        o1 += a * w.y;
    }

    // ---- pointwise update
    float betav = betap[0];
    float2 hv = *(const float2*)(h_in + (size_t)node * HIDDEN + c0i);
    float2 xv = *(const float2*)(g_x0 + (size_t)node * HIDDEN + c0i);
    float ex0 = ext_s[c0i], ex1 = ext_s[c0i + 1];
    float u0 = hv.x + STEP_F * fmaxf(o0 - hv.x * ex0 + xv.x * betav, 0.0f);
    float u1 = hv.y + STEP_F * fmaxf(o1 - hv.y * ex1 + xv.y * betav, 0.0f);

    if (!LAST) {
        *(float2*)(h_out + (size_t)node * HIDDEN + c0i) = make_float2(u0, u1);
    } else {
        // ---- decoder matvec: out[c] = sum_k u[k] * dec[c][k]
        __syncwarp();
        agg_s[warp][c0i]     = u0;
        agg_s[warp][c0i + 1] = u1;
        __syncwarp();
        float d0 = 0.0f, d1 = 0.0f;
#pragma unroll
        for (int k = 0; k < HIDDEN; k++) {
            float u = agg_s[warp][k];                     // broadcast
            d0 += u * dec_s[k * NUM_CLASSES + lane];
            if (lane < NUM_CLASSES - 32)
                d1 += u * dec_s[k * NUM_CLASSES + 32 + lane];
        }
        out[(size_t)node * NUM_CLASSES + lane] = d0;
        if (lane < NUM_CLASSES - 32)
            out[(size_t)node * NUM_CLASSES + 32 + lane] = d1;
    }
}

// ---------------- launch ----------------
extern "C" void kernel_launch(void* const* d_in, const int* in_sizes, int n_in,
                              void* d_out, int out_size) {
    const float* x    = (const float*)d_in[0];   // [50000, 500]
    const int*   ei   = (const int*)  d_in[1];   // [2, 1600000]
    const float* enc  = (const float*)d_in[2];   // [64, 500]
    const float* dec  = (const float*)d_in[3];   // [40, 64]
    const float* ext  = (const float*)d_in[4];   // [1, 64]
    const float* beta = (const float*)d_in[5];   // [1]
    const float* pw   = (const float*)d_in[6];   // [64, 66]
    float* out = (float*)d_out;                  // [50000, 40]

    const int* erow = ei;
    const int* ecol = ei + N_EDGES;

    // graph preprocessing (CSR by destination)
    zero_counts<<<(N_NODES + 255) / 256, 256>>>();
    count_deg<<<(N_EDGES + 255) / 256, 256>>>(ecol);
    deg_inv_kernel<<<(N_NODES + 255) / 256, 256>>>();
    scan1<<<SCAN_NBLK, SCAN_BLK>>>();
    scan2<<<1, 32>>>();
    scan3<<<(N_NODES + 255) / 256, 256>>>();
    fill_csr<<<(N_EDGES + 255) / 256, 256>>>(erow, ecol);
    weff_kernel<<<1, 64>>>(pw);

    // encoder: h_a = x0 = x @ enc_w^T
    encoder_gemm<<<(N_NODES + BM - 1) / BM, 256>>>(x, enc);

    // 4 fused propagation layers (ping-pong h), last also applies decoder
    int lgrid = (N_NODES + 7) / 8;
    layer_kernel<true,  false><<<lgrid, 256>>>(ext, beta, dec, out);
    layer_kernel<false, false><<<lgrid, 256>>>(ext, beta, dec, out);
    layer_kernel<true,  false><<<lgrid, 256>>>(ext, beta, dec, out);
    layer_kernel<false, true ><<<lgrid, 256>>>(ext, beta, dec, out);
}

// round 4
// speedup vs baseline: 1.1746x; 1.1746x over previous
#include <cuda_runtime.h>
#include <cuda_bf16.h>
#include <cstdint>

#define N_NODES 50000
#define N_EDGES 1600000
#define NUM_FEATURES 500
#define HIDDEN 64
#define NUM_CLASSES 40
#define NUM_LAYERS 4
#define STEP_F 0.1f

#define SCAN_BLK 1024
#define SCAN_NBLK ((N_NODES + SCAN_BLK - 1) / SCAN_BLK)   // 49

// ---------------- device scratch (static, allocation-free) ----------------
__device__ float g_h[N_NODES * HIDDEN];
__device__ float g_x0[N_NODES * HIDDEN];
__device__ float g_agg[N_NODES * HIDDEN];
__device__ __align__(128) __nv_bfloat162 g_hbf[N_NODES * (HIDDEN / 2)];  // bf16 mirror of h
__device__ unsigned long long g_srccoef[N_EDGES];   // packed {src, coef}
__device__ int   g_rowptr[N_NODES + 1];
__device__ int   g_degcnt[N_NODES];
__device__ int   g_fill[N_NODES];
__device__ float g_deginv[N_NODES];
__device__ float g_W[HIDDEN * HIDDEN];
__device__ int   g_blocksums[SCAN_NBLK];
__device__ int   g_blockoff[SCAN_NBLK];

// ---------------- graph preprocessing ----------------
__global__ void zero_counts() {
    int i = blockIdx.x * blockDim.x + threadIdx.x;
    if (i < N_NODES) { g_degcnt[i] = 0; g_fill[i] = 0; }
}

__global__ void count_deg(const int* __restrict__ col) {
    int e = blockIdx.x * blockDim.x + threadIdx.x;
    if (e < N_EDGES) atomicAdd(&g_degcnt[col[e]], 1);
}

__global__ void deg_inv_kernel() {
    int i = blockIdx.x * blockDim.x + threadIdx.x;
    if (i < N_NODES) {
        int c = g_degcnt[i];
        g_deginv[i] = (c > 0) ? rsqrtf((float)c) : 0.0f;
    }
}

// ---- multi-block exclusive scan of g_degcnt -> g_rowptr ----
__global__ void scan1() {
    __shared__ int s[SCAN_BLK];
    int b = blockIdx.x, t = threadIdx.x;
    int i = b * SCAN_BLK + t;
    int v = (i < N_NODES) ? g_degcnt[i] : 0;
    s[t] = v;
    __syncthreads();
#pragma unroll
    for (int off = 1; off < SCAN_BLK; off <<= 1) {
        int tv = 0;
        if (t >= off) tv = s[t - off];
        __syncthreads();
        if (t >= off) s[t] += tv;
        __syncthreads();
    }
    if (i < N_NODES) g_rowptr[i] = s[t] - v;     // block-local exclusive
    if (t == SCAN_BLK - 1) g_blocksums[b] = s[t];
}

__global__ void scan2() {
    if (threadIdx.x == 0) {
        int run = 0;
        for (int b = 0; b < SCAN_NBLK; b++) {
            g_blockoff[b] = run;
            run += g_blocksums[b];
        }
        g_rowptr[N_NODES] = run;
    }
}

__global__ void scan3() {
    int i = blockIdx.x * blockDim.x + threadIdx.x;
    if (i < N_NODES) g_rowptr[i] += g_blockoff[i >> 10];
}

__global__ void fill_csr(const int* __restrict__ row, const int* __restrict__ col) {
    int e = blockIdx.x * blockDim.x + threadIdx.x;
    if (e >= N_EDGES) return;
    int v = col[e];
    int r = row[e];
    int slot = g_rowptr[v] + atomicAdd(&g_fill[v], 1);
    float cf = g_deginv[r] * g_deginv[v];
    g_srccoef[slot] = (unsigned long long)(unsigned)r
                    | ((unsigned long long)__float_as_uint(cf) << 32);
}

// ---------------- pairwise weight: W_eff = sym(triu(pw,1)) + diag(q*rowsum|W|+r)
__global__ void weff_kernel(const float* __restrict__ pw) {
    int i = threadIdx.x;
    if (i >= HIDDEN) return;
    float q  = pw[i * (HIDDEN + 2) + HIDDEN];
    float rr = pw[i * (HIDDEN + 2) + HIDDEN + 1];
    float s = 0.0f;
    for (int j = 0; j < HIDDEN; j++) {
        float w = 0.0f;
        if (i < j)      w = pw[i * (HIDDEN + 2) + j];
        else if (i > j) w = pw[j * (HIDDEN + 2) + i];
        s += fabsf(w);
        g_W[i * HIDDEN + j] = w;
    }
    g_W[i * HIDDEN + i] = q * s + rr;
}

// ---------------- edge aggregation: agg[v] = sum coef * h_bf16[src]
// one warp per node; 32 lanes cover the 64-bf16 row (128B = ONE cache line).
__global__ void gather_kernel() {
    int gw   = (blockIdx.x * blockDim.x + threadIdx.x) >> 5;
    int lane = threadIdx.x & 31;
    if (gw >= N_NODES) return;
    int beg = g_rowptr[gw];
    int end = g_rowptr[gw + 1];
    float2 acc = make_float2(0.0f, 0.0f);
    const __nv_bfloat162* __restrict__ hb = g_hbf;
    int e = beg;
    for (; e + 3 < end; e += 4) {
        unsigned long long p0 = __ldg(&g_srccoef[e]);
        unsigned long long p1 = __ldg(&g_srccoef[e + 1]);
        unsigned long long p2 = __ldg(&g_srccoef[e + 2]);
        unsigned long long p3 = __ldg(&g_srccoef[e + 3]);
        __nv_bfloat162 b0 = __ldg(hb + (size_t)(unsigned)(p0 & 0xffffffffu) * 32 + lane);
        __nv_bfloat162 b1 = __ldg(hb + (size_t)(unsigned)(p1 & 0xffffffffu) * 32 + lane);
        __nv_bfloat162 b2 = __ldg(hb + (size_t)(unsigned)(p2 & 0xffffffffu) * 32 + lane);
        __nv_bfloat162 b3 = __ldg(hb + (size_t)(unsigned)(p3 & 0xffffffffu) * 32 + lane);
        float c0 = __uint_as_float((unsigned)(p0 >> 32));
        float c1 = __uint_as_float((unsigned)(p1 >> 32));
        float c2 = __uint_as_float((unsigned)(p2 >> 32));
        float c3 = __uint_as_float((unsigned)(p3 >> 32));
        float2 v0 = __bfloat1622float2(b0);
        float2 v1 = __bfloat1622float2(b1);
        float2 v2 = __bfloat1622float2(b2);
        float2 v3 = __bfloat1622float2(b3);
        acc.x += c0 * v0.x; acc.y += c0 * v0.y;
        acc.x += c1 * v1.x; acc.y += c1 * v1.y;
        acc.x += c2 * v2.x; acc.y += c2 * v2.y;
        acc.x += c3 * v3.x; acc.y += c3 * v3.y;
    }
    for (; e < end; e++) {
        unsigned long long p0 = __ldg(&g_srccoef[e]);
        __nv_bfloat162 b0 = __ldg(hb + (size_t)(unsigned)(p0 & 0xffffffffu) * 32 + lane);
        float c0 = __uint_as_float((unsigned)(p0 >> 32));
        float2 v0 = __bfloat1622float2(b0);
        acc.x += c0 * v0.x; acc.y += c0 * v0.y;
    }
    *(float2*)(g_agg + (size_t)gw * HIDDEN + lane * 2) = acc;
}

// ---------------- register-tiled SGEMM: C[M,N] = A[M,K] @ B[N,K]^T, fused epilogues
// MODE 0: encoder (A=x, B=enc_w)   -> writes g_h, g_x0, g_hbf
// MODE 1: layer   (A=g_agg, B=g_W) -> g_h += STEP*relu(acc - h*ext + x0*beta); also g_hbf
// MODE 2: decoder (A=g_h, B=dec_w) -> writes Cout
#define BM 128
#define BN 64
#define BK 16
#define TM 8
#define TN 4

__device__ __forceinline__ void store_bf_pair(int row, int col, float4 u) {
    __nv_bfloat162 b0 = __floats2bfloat162_rn(u.x, u.y);
    __nv_bfloat162 b1 = __floats2bfloat162_rn(u.z, u.w);
    uint2 pk;
    pk.x = *(unsigned*)&b0;
    pk.y = *(unsigned*)&b1;
    *(uint2*)&g_hbf[(size_t)row * 32 + (col >> 1)] = pk;
}

template <int MODE>
__global__ void gemm_nt(const float* __restrict__ Ap, const float* __restrict__ Bp,
                        float* __restrict__ Cout,
                        int M, int N, int K,
                        const float* __restrict__ ext, const float* __restrict__ betap) {
    __shared__ float As[BK][BM + 4];
    __shared__ float Bs[BK][BN + 4];

    const float* A = (MODE == 0) ? Ap : ((MODE == 1) ? (const float*)g_agg : (const float*)g_h);
    const float* B = (MODE == 1) ? (const float*)g_W : Bp;

    int tid = threadIdx.x;        // 256 threads
    int tx = tid & 15;            // 16 col groups of TN=4
    int ty = tid >> 4;            // 16 row groups of TM=8
    int bm0 = blockIdx.x * BM;

    float acc[TM][TN];
#pragma unroll
    for (int r = 0; r < TM; r++)
#pragma unroll
        for (int c = 0; c < TN; c++) acc[r][c] = 0.0f;

    for (int kb = 0; kb < K; kb += BK) {
#pragma unroll
        for (int it = 0; it < 2; it++) {
            int j = tid + it * 256;
            int arow = j >> 2;
            int kc4 = (j & 3) * 4;
            int grow = bm0 + arow;
#pragma unroll
            for (int i = 0; i < 4; i++) {
                int gc = kb + kc4 + i;
                float v = (grow < M && gc < K) ? A[(size_t)grow * K + gc] : 0.0f;
                As[kc4 + i][arow] = v;
            }
        }
        {
            int j = tid;
            int nrow = j >> 2;
            int kc4 = (j & 3) * 4;
#pragma unroll
            for (int i = 0; i < 4; i++) {
                int gc = kb + kc4 + i;
                float v = (nrow < N && gc < K) ? B[(size_t)nrow * K + gc] : 0.0f;
                Bs[kc4 + i][nrow] = v;
            }
        }
        __syncthreads();
#pragma unroll
        for (int k = 0; k < BK; k++) {
            float4 a0 = *(const float4*)&As[k][ty * TM];
            float4 a1 = *(const float4*)&As[k][ty * TM + 4];
            float4 b  = *(const float4*)&Bs[k][tx * TN];
            float ar[TM] = {a0.x, a0.y, a0.z, a0.w, a1.x, a1.y, a1.z, a1.w};
            float bc[TN] = {b.x, b.y, b.z, b.w};
#pragma unroll
            for (int r = 0; r < TM; r++)
#pragma unroll
                for (int c = 0; c < TN; c++)
                    acc[r][c] += ar[r] * bc[c];
        }
        __syncthreads();
    }

    int col = tx * TN;
    if (col >= N) return;   // N % 4 == 0 in all uses

    float betav = 0.0f;
    float4 extv = make_float4(0.f, 0.f, 0.f, 0.f);
    if (MODE == 1) {
        betav = betap[0];
        extv = *(const float4*)&ext[col];
    }

#pragma unroll
    for (int r = 0; r < TM; r++) {
        int row = bm0 + ty * TM + r;
        if (row >= M) continue;
        float4 o = make_float4(acc[r][0], acc[r][1], acc[r][2], acc[r][3]);
        if (MODE == 0) {
            *(float4*)&g_h[(size_t)row * HIDDEN + col]  = o;
            *(float4*)&g_x0[(size_t)row * HIDDEN + col] = o;
            store_bf_pair(row, col, o);
        } else if (MODE == 1) {
            float4 hv = *(const float4*)&g_h[(size_t)row * HIDDEN + col];
            float4 xv = *(const float4*)&g_x0[(size_t)row * HIDDEN + col];
            float4 u;
            u.x = hv.x + STEP_F * fmaxf(o.x - hv.x * extv.x + xv.x * betav, 0.0f);
            u.y = hv.y + STEP_F * fmaxf(o.y - hv.y * extv.y + xv.y * betav, 0.0f);
            u.z = hv.z + STEP_F * fmaxf(o.z - hv.z * extv.z + xv.z * betav, 0.0f);
            u.w = hv.w + STEP_F * fmaxf(o.w - hv.w * extv.w + xv.w * betav, 0.0f);
            *(float4*)&g_h[(size_t)row * HIDDEN + col] = u;
            store_bf_pair(row, col, u);
        } else {
            *(float4*)&Cout[(size_t)row * N + col] = o;
        }
    }
}

// ---------------- launch ----------------
extern "C" void kernel_launch(void* const* d_in, const int* in_sizes, int n_in,
                              void* d_out, int out_size) {
    const float* x    = (const float*)d_in[0];   // [50000, 500]
    const int*   ei   = (const int*)  d_in[1];   // [2, 1600000]
    const float* enc  = (const float*)d_in[2];   // [64, 500]
    const float* dec  = (const float*)d_in[3];   // [40, 64]
    const float* ext  = (const float*)d_in[4];   // [1, 64]
    const float* beta = (const float*)d_in[5];   // [1]
    const float* pw   = (const float*)d_in[6];   // [64, 66]
    float* out = (float*)d_out;                  // [50000, 40]

    const int* erow = ei;
    const int* ecol = ei + N_EDGES;

    // graph preprocessing (CSR by destination)
    zero_counts<<<(N_NODES + 255) / 256, 256>>>();
    count_deg<<<(N_EDGES + 255) / 256, 256>>>(ecol);
    deg_inv_kernel<<<(N_NODES + 255) / 256, 256>>>();
    scan1<<<SCAN_NBLK, SCAN_BLK>>>();
    scan2<<<1, 32>>>();
    scan3<<<(N_NODES + 255) / 256, 256>>>();
    fill_csr<<<(N_EDGES + 255) / 256, 256>>>(erow, ecol);
    weff_kernel<<<1, 64>>>(pw);

    int ggrid = (N_NODES + BM - 1) / BM;

    // encoder: h = x0 = x @ enc_w^T (+ bf16 mirror)
    gemm_nt<0><<<ggrid, 256>>>(x, enc, nullptr, N_NODES, HIDDEN, NUM_FEATURES,
                               nullptr, nullptr);

    // 4 propagation layers
    for (int l = 0; l < NUM_LAYERS; l++) {
        gather_kernel<<<(N_NODES * 32 + 255) / 256, 256>>>();
        gemm_nt<1><<<ggrid, 256>>>(nullptr, nullptr, nullptr,
                                   N_NODES, HIDDEN, HIDDEN, ext, beta);
    }

    // decoder: out = h @ dec_w^T
    gemm_nt<2><<<ggrid, 256>>>(nullptr, dec, out, N_NODES, NUM_CLASSES, HIDDEN,
                               nullptr, nullptr);
}